// round 5
// baseline (speedup 1.0000x reference)
#include <cuda_runtime.h>
#include <cuda_fp16.h>
#include <cstdint>

// out[256,64] = haar_dwt2(x[256,262144]) @ W[64,262144]^T + b
// Factorized: out = x @ W'^T + b with W' = adjoint-Haar(W), stored fp16.
// GEMM: mma.sync m16n8k16 fp16 (single-term A and B, fp32 accum),
// split-K 64 x 2 M-tiles; A and B both via 4-stage cp.async pipeline.

#define IN_FEATS (1 << 18)            // 262144
#define BATCH    256
#define NOUT     64
#define KSPLIT   64
#define KC       (IN_FEATS / KSPLIT)  // 4096
#define BK       32
#define NB       (KC / BK)            // 128
#define BSTRIDE  80                   // B smem row pitch (bytes)
#define ASTG     16384                // A stage: 8 segs x 256 thr x 8B
#define BSTG     (64 * BSTRIDE)       // 5120
#define STG      (ASTG + BSTG)        // 21504
#define NSTG     4
#define SMEM_ALLOC (NSTG * STG)       // 86016

__device__ __half g_Wp[NOUT * IN_FEATS];           // 33.5 MB  W' fp16
__device__ float  g_part[KSPLIT * BATCH * NOUT];   // 4 MB split-K partials

// ---------------- helpers ----------------
__device__ __forceinline__ uint32_t smem_u32(const void* p) {
    uint32_t a;
    asm("{ .reg .u64 t; cvta.to.shared.u64 t, %1; cvt.u32.u64 %0, t; }"
        : "=r"(a) : "l"(p));
    return a;
}
__device__ __forceinline__ void cp_async16(uint32_t dst, const void* src) {
    asm volatile("cp.async.cg.shared.global [%0], [%1], 16;"
                 :: "r"(dst), "l"(src) : "memory");
}
__device__ __forceinline__ void cp_async8(uint32_t dst, const void* src) {
    asm volatile("cp.async.ca.shared.global [%0], [%1], 8;"
                 :: "r"(dst), "l"(src) : "memory");
}
__device__ __forceinline__ void cp_commit() {
    asm volatile("cp.async.commit_group;" ::: "memory");
}
template <int N>
__device__ __forceinline__ void cp_wait() {
    asm volatile("cp.async.wait_group %0;" :: "n"(N) : "memory");
}
__device__ __forceinline__ void mma_fp16(float* d, const uint32_t* a,
                                         const uint32_t* b) {
    asm volatile(
        "mma.sync.aligned.m16n8k16.row.col.f32.f16.f16.f32 "
        "{%0,%1,%2,%3}, {%4,%5,%6,%7}, {%8,%9}, {%0,%1,%2,%3};"
        : "+f"(d[0]), "+f"(d[1]), "+f"(d[2]), "+f"(d[3])
        : "r"(a[0]), "r"(a[1]), "r"(a[2]), "r"(a[3]), "r"(b[0]), "r"(b[1]));
}
#define LDMX4(r0, r1, r2, r3, addr)                                          \
    asm volatile("ldmatrix.sync.aligned.m8n8.x4.shared.b16 {%0,%1,%2,%3}, [%4];" \
                 : "=r"(r0), "=r"(r1), "=r"(r2), "=r"(r3) : "r"(addr))
__device__ __forceinline__ uint32_t h2u(__half2 h) { return *(uint32_t*)&h; }

// ---------- Kernel 1: W' = adjoint-DWT(W), fp16, 8 outputs/thread ----------
__global__ __launch_bounds__(256) void k_wtransform(const float* __restrict__ W) {
    int t   = blockIdx.x * 256 + threadIdx.x;
    int idx = t << 3;
    int n    = idx >> 18;
    int rem  = idx & (IN_FEATS - 1);
    int c    = rem >> 16;
    int r    = (rem >> 8) & 255;
    int colb = rem & 255;                 // multiple of 8
    int p = r >> 1, q0 = colb >> 1;       // q0 multiple of 4

    const float* base = W + ((size_t)n << 18) + (c << 16) + (p << 7) + q0;
    float4 LL = *(const float4*)(base);
    float4 LH = *(const float4*)(base + 16384);
    float4 HL = *(const float4*)(base + 32768);
    float4 HH = *(const float4*)(base + 49152);

    float rs = (r & 1) ? -1.0f : 1.0f;
    float e0 = LL.x + rs * LH.x, f0 = HL.x + rs * HH.x;
    float e1 = LL.y + rs * LH.y, f1 = HL.y + rs * HH.y;
    float e2 = LL.z + rs * LH.z, f2 = HL.z + rs * HH.z;
    float e3 = LL.w + rs * LH.w, f3 = HL.w + rs * HH.w;

    uint4 o;
    o.x = h2u(__floats2half2_rn(0.5f * (e0 + f0), 0.5f * (e0 - f0)));
    o.y = h2u(__floats2half2_rn(0.5f * (e1 + f1), 0.5f * (e1 - f1)));
    o.z = h2u(__floats2half2_rn(0.5f * (e2 + f2), 0.5f * (e2 - f2)));
    o.w = h2u(__floats2half2_rn(0.5f * (e3 + f3), 0.5f * (e3 - f3)));
    *(uint4*)(g_Wp + idx) = o;
}

// ---------- Kernel 2: mma.sync fp16 split-K GEMM ----------
// Grid (KSPLIT, 2). CTA 256 thr = 8 warps, warp tile 16(m) x 64(n).
// A: cp.async fp32 into per-thread 8B slots (4-stage ring), convert at use.
// B: cp.async fp16 rows (pitch 80B), ldmatrix.x4.
__global__ __launch_bounds__(256, 1) void k_gemm_mma(const float* __restrict__ x) {
    extern __shared__ __align__(128) char sm[];
    uint32_t sb = smem_u32(sm);
    int tid = threadIdx.x, l = tid & 31, wid = tid >> 5;
    int ks = blockIdx.x, mt = blockIdx.y;

    // A fragment ownership: rows r0, r0+8; k-pair cols q+8p (p=0..3)
    int r0 = wid * 16 + (l >> 2), q = (l & 3) * 2;
    // seg = p*2 + s  (s: row r0 vs r0+8); src pointers per seg
    const float* asrc[8];
#pragma unroll
    for (int p = 0; p < 4; p++)
#pragma unroll
        for (int s = 0; s < 2; s++)
            asrc[p * 2 + s] = x + (size_t)(mt * 128 + r0 + 8 * s) * IN_FEATS
                                + (size_t)ks * KC + q + 8 * p;
    uint32_t a_slot = sb + tid * 8;             // + stage + seg*2048

    // B cp.async: thread -> row tid>>2 (64 rows), 16B chunk tid&3
    int brow = tid >> 2, bc = tid & 3;
    const __half* bsrc = g_Wp + (size_t)brow * IN_FEATS + (size_t)ks * KC + bc * 8;
    uint32_t bdst = sb + ASTG + brow * BSTRIDE + bc * 16;

    // ldmatrix lane base (within B stage)
    int g = l >> 3, li = l & 7;
    uint32_t lm_base = sb + ASTG + (uint32_t)(li + (g >> 1) * 8) * BSTRIDE
                       + (g & 1) * 16;

    float acc[8][4];
#pragma unroll
    for (int f = 0; f < 8; f++)
#pragma unroll
        for (int i = 0; i < 4; i++) acc[f][i] = 0.0f;

#define ISSUE_CP(jb, stg)                                                   \
    do {                                                                    \
        uint32_t so_ = (stg);                                               \
        int ko_ = (jb) * BK;                                                \
        _Pragma("unroll")                                                   \
        for (int sg = 0; sg < 8; sg++)                                      \
            cp_async8(a_slot + so_ + sg * 2048, asrc[sg] + ko_);            \
        cp_async16(bdst + so_, bsrc + ko_);                                 \
    } while (0)

    // prologue: stages 0..2
#pragma unroll
    for (int s = 0; s < NSTG - 1; s++) {
        ISSUE_CP(s, s * STG);
        cp_commit();
    }

    for (int jb = 0; jb < NB; jb++) {
        uint32_t stg = (uint32_t)(jb & (NSTG - 1)) * STG;
        cp_wait<NSTG - 2>();
        __syncthreads();

        // refill stage (jb+3)&3 (its previous contents were consumed at jb-1)
        if (jb + NSTG - 1 < NB)
            ISSUE_CP(jb + NSTG - 1, (uint32_t)((jb + NSTG - 1) & (NSTG - 1)) * STG);
        cp_commit();

        // A: LDS fp32 pairs from own slots, convert to fp16 frags
        uint32_t ah[2][4];
#pragma unroll
        for (int k0 = 0; k0 < 2; k0++)
#pragma unroll
            for (int i = 0; i < 4; i++) {
                float2 v;
                asm volatile("ld.shared.v2.f32 {%0,%1}, [%2];"
                             : "=f"(v.x), "=f"(v.y)
                             : "r"(a_slot + stg + (4 * k0 + i) * 2048));
                ah[k0][i] = h2u(__floats2half2_rn(v.x, v.y));
            }

        // B frags via ldmatrix + mma (single term)
#pragma unroll
        for (int k0 = 0; k0 < 2; k0++) {
#pragma unroll
            for (int fp = 0; fp < 4; fp++) {
                uint32_t b0, b1, b2, b3;
                LDMX4(b0, b1, b2, b3, lm_base + stg + fp * (16 * BSTRIDE) + k0 * 32);
                uint32_t bf0[2] = {b0, b1}, bf1[2] = {b2, b3};
                mma_fp16(acc[fp * 2],     ah[k0], bf0);
                mma_fp16(acc[fp * 2 + 1], ah[k0], bf1);
            }
        }
    }

    // epilogue: split-K partials
    int gm0 = mt * 128 + r0;
    float* pbase = g_part + ((size_t)ks * BATCH + gm0) * NOUT;
#pragma unroll
    for (int f = 0; f < 8; f++) {
        int n = f * 8 + q;
        *(float2*)(pbase + n)            = make_float2(acc[f][0], acc[f][1]);
        *(float2*)(pbase + 8 * NOUT + n) = make_float2(acc[f][2], acc[f][3]);
    }
}

// ---------- Kernel 3: reduce split-K partials + bias ----------
__global__ __launch_bounds__(256) void k_reduce(const float* __restrict__ bias,
                                                float* __restrict__ out) {
    int t = blockIdx.x * 256 + threadIdx.x;     // 0..16383
    float s = bias[t & (NOUT - 1)];
    const float* p = g_part + t;
#pragma unroll 16
    for (int ks = 0; ks < KSPLIT; ks++)
        s += p[(size_t)ks * BATCH * NOUT];
    out[t] = s;
}

extern "C" void kernel_launch(void* const* d_in, const int* in_sizes, int n_in,
                              void* d_out, int out_size) {
    const float* x = (const float*)d_in[0];
    const float* W = (const float*)d_in[1];
    const float* b = (const float*)d_in[2];

    cudaFuncSetAttribute(k_gemm_mma, cudaFuncAttributeMaxDynamicSharedMemorySize,
                         SMEM_ALLOC);

    k_wtransform<<<(NOUT * IN_FEATS / 8) / 256, 256>>>(W);
    k_gemm_mma<<<dim3(KSPLIT, BATCH / 128), 256, SMEM_ALLOC>>>(x);
    k_reduce<<<(BATCH * NOUT) / 256, 256>>>(b, (float*)d_out);
}

// round 6
// speedup vs baseline: 1.3707x; 1.3707x over previous
#include <cuda_runtime.h>
#include <cuda_fp16.h>
#include <cstdint>

// out[256,64] = haar_dwt2(x[256,262144]) @ W[64,262144]^T + b
// Factorized: out = x @ W'^T + b with W' = adjoint-Haar(W), stored fp16.
// GEMM: mma.sync m16n8k16 fp16 (fp32 accum), split-K 64 x 2 M-tiles.
// A staged fp32 row-major + XOR chunk swizzle (coalesced cp.async, conflict-
// free LDS), B fp16 pitch-80 rows + ldmatrix. 6-stage cp.async ring, 512 thr.

#define IN_FEATS (1 << 18)            // 262144
#define BATCH    256
#define NOUT     64
#define KSPLIT   64
#define KC       (IN_FEATS / KSPLIT)  // 4096
#define BK       32
#define NB       (KC / BK)            // 128
#define ASTG     16384                // A stage: 128 rows x 128 B
#define BSTRIDE  80
#define BSTG     (64 * BSTRIDE)       // 5120
#define STG      (ASTG + BSTG)        // 21504
#define NSTG     6
#define SMEM_ALLOC (NSTG * STG)       // 129024

__device__ __half g_Wp[NOUT * IN_FEATS];           // 33.5 MB  W' fp16
__device__ float  g_part[KSPLIT * BATCH * NOUT];   // 4 MB split-K partials

// ---------------- helpers ----------------
__device__ __forceinline__ uint32_t smem_u32(const void* p) {
    uint32_t a;
    asm("{ .reg .u64 t; cvta.to.shared.u64 t, %1; cvt.u32.u64 %0, t; }"
        : "=r"(a) : "l"(p));
    return a;
}
__device__ __forceinline__ void cp_async16(uint32_t dst, const void* src) {
    asm volatile("cp.async.cg.shared.global [%0], [%1], 16;"
                 :: "r"(dst), "l"(src) : "memory");
}
__device__ __forceinline__ void cp_commit() {
    asm volatile("cp.async.commit_group;" ::: "memory");
}
template <int N>
__device__ __forceinline__ void cp_wait() {
    asm volatile("cp.async.wait_group %0;" :: "n"(N) : "memory");
}
__device__ __forceinline__ void mma_fp16(float* d, const uint32_t* a,
                                         const uint32_t* b) {
    asm volatile(
        "mma.sync.aligned.m16n8k16.row.col.f32.f16.f16.f32 "
        "{%0,%1,%2,%3}, {%4,%5,%6,%7}, {%8,%9}, {%0,%1,%2,%3};"
        : "+f"(d[0]), "+f"(d[1]), "+f"(d[2]), "+f"(d[3])
        : "r"(a[0]), "r"(a[1]), "r"(a[2]), "r"(a[3]), "r"(b[0]), "r"(b[1]));
}
#define LDMX4(r0, r1, r2, r3, addr)                                          \
    asm volatile("ldmatrix.sync.aligned.m8n8.x4.shared.b16 {%0,%1,%2,%3}, [%4];" \
                 : "=r"(r0), "=r"(r1), "=r"(r2), "=r"(r3) : "r"(addr))
__device__ __forceinline__ uint32_t h2u(__half2 h) { return *(uint32_t*)&h; }

// ---------- Kernel 1: W' = adjoint-DWT(W), fp16, 8 outputs/thread ----------
__global__ __launch_bounds__(256) void k_wtransform(const float* __restrict__ W) {
    int t   = blockIdx.x * 256 + threadIdx.x;
    int idx = t << 3;
    int n    = idx >> 18;
    int rem  = idx & (IN_FEATS - 1);
    int c    = rem >> 16;
    int r    = (rem >> 8) & 255;
    int colb = rem & 255;
    int p = r >> 1, q0 = colb >> 1;

    const float* base = W + ((size_t)n << 18) + (c << 16) + (p << 7) + q0;
    float4 LL = *(const float4*)(base);
    float4 LH = *(const float4*)(base + 16384);
    float4 HL = *(const float4*)(base + 32768);
    float4 HH = *(const float4*)(base + 49152);

    float rs = (r & 1) ? -1.0f : 1.0f;
    float e0 = LL.x + rs * LH.x, f0 = HL.x + rs * HH.x;
    float e1 = LL.y + rs * LH.y, f1 = HL.y + rs * HH.y;
    float e2 = LL.z + rs * LH.z, f2 = HL.z + rs * HH.z;
    float e3 = LL.w + rs * LH.w, f3 = HL.w + rs * HH.w;

    uint4 o;
    o.x = h2u(__floats2half2_rn(0.5f * (e0 + f0), 0.5f * (e0 - f0)));
    o.y = h2u(__floats2half2_rn(0.5f * (e1 + f1), 0.5f * (e1 - f1)));
    o.z = h2u(__floats2half2_rn(0.5f * (e2 + f2), 0.5f * (e2 - f2)));
    o.w = h2u(__floats2half2_rn(0.5f * (e3 + f3), 0.5f * (e3 - f3)));
    *(uint4*)(g_Wp + idx) = o;
}

// ---------- Kernel 2: mma.sync fp16 split-K GEMM ----------
// Grid (KSPLIT, 2). CTA 512 thr = 16 warps, warp tile 16(m) x 32(n).
__global__ __launch_bounds__(512, 1) void k_gemm_mma(const float* __restrict__ x) {
    extern __shared__ __align__(128) char sm[];
    uint32_t sb = smem_u32(sm);
    int tid = threadIdx.x, l = tid & 31, wid = tid >> 5;
    int ks = blockIdx.x, mt = blockIdx.y;
    int wm = wid >> 1, wn = wid & 1;

    // ---- A staging: slot tid (+512): row=slot>>3, chunk c=slot&7 ----
    int arow = tid >> 3, ac = tid & 7;
    const float* a_src0 = x + (size_t)(mt * 128 + arow) * IN_FEATS
                            + (size_t)ks * KC + ac * 4;
    const float* a_src1 = a_src0 + (size_t)64 * IN_FEATS;    // row + 64
    uint32_t swz = (uint32_t)(ac ^ (arow & 7)) << 4;
    uint32_t a_dst0 = sb + (uint32_t)arow * 128 + swz;
    uint32_t a_dst1 = a_dst0 + 64 * 128;                     // (row+64)&7 same

    // ---- B staging: tid<256: row tid>>2, 16B chunk tid&3 ----
    int brow = (tid & 255) >> 2, bc = tid & 3;
    const __half* b_src = g_Wp + (size_t)brow * IN_FEATS + (size_t)ks * KC + bc * 8;
    uint32_t b_dst = sb + ASTG + (uint32_t)brow * BSTRIDE + bc * 16;
    bool has_b = (tid < 256);

    // ---- fragment read bases ----
    int r0 = wm * 16 + (l >> 2), q = (l & 3) * 2;
    int cb = (l >> 1) & 1, rw = r0 & 7;
    uint32_t arb = sb + (uint32_t)r0 * 128 + (l & 1) * 8;    // + stg + chunk<<4 (+1024 row+8)
    // B ldmatrix base: rows wn*32 + fp*16 + (l&7) + ((l>>4)&1)*8, chunk (l>>3)&1
    uint32_t lm_base = sb + ASTG
                     + (uint32_t)(wn * 32 + (l & 7) + ((l >> 4) & 1) * 8) * BSTRIDE
                     + (((l >> 3) & 1) << 4);

    float acc[4][4];
#pragma unroll
    for (int f = 0; f < 4; f++)
#pragma unroll
        for (int i = 0; i < 4; i++) acc[f][i] = 0.0f;

#define ISSUE_CP(jb, so)                                                    \
    do {                                                                    \
        int ko_ = (jb) * BK;                                                \
        cp_async16(a_dst0 + (so), a_src0 + ko_);                            \
        cp_async16(a_dst1 + (so), a_src1 + ko_);                            \
        if (has_b) cp_async16(b_dst + (so), b_src + ko_);                   \
    } while (0)

    // prologue: stages 0..NSTG-2
#pragma unroll
    for (int s = 0; s < NSTG - 1; s++) {
        ISSUE_CP(s, (uint32_t)s * STG);
        cp_commit();
    }

    uint32_t cur = 0, pre = (NSTG - 1) * STG;
    for (int jb = 0; jb < NB; jb++) {
        cp_wait<NSTG - 2>();
        __syncthreads();

        if (jb + NSTG - 1 < NB) ISSUE_CP(jb + NSTG - 1, pre);
        cp_commit();

#pragma unroll
        for (int k0 = 0; k0 < 2; k0++) {
            // A fragments: rows r0 / r0+8, col pairs q+16k0, q+8+16k0
            uint32_t ah[4];
            uint32_t c0 = (uint32_t)((cb + 4 * k0) ^ rw) << 4;
            uint32_t c1 = (uint32_t)((cb + 4 * k0 + 2) ^ rw) << 4;
#pragma unroll
            for (int i = 0; i < 4; i++) {
                uint32_t addr = arb + cur + ((i & 1) ? 1024u : 0u)
                              + ((i & 2) ? c1 : c0);
                float2 v;
                asm volatile("ld.shared.v2.f32 {%0,%1}, [%2];"
                             : "=f"(v.x), "=f"(v.y) : "r"(addr));
                ah[i] = h2u(__floats2half2_rn(v.x, v.y));
            }
#pragma unroll
            for (int fp = 0; fp < 2; fp++) {
                uint32_t b0, b1, b2, b3;
                LDMX4(b0, b1, b2, b3, lm_base + cur + fp * (16 * BSTRIDE) + k0 * 32);
                uint32_t bf0[2] = {b0, b1}, bf1[2] = {b2, b3};
                mma_fp16(acc[fp * 2],     ah, bf0);
                mma_fp16(acc[fp * 2 + 1], ah, bf1);
            }
        }

        cur += STG; if (cur == NSTG * STG) cur = 0;
        pre += STG; if (pre == NSTG * STG) pre = 0;
    }

    // epilogue: split-K partials
    int gm0 = mt * 128 + r0;
    float* pbase = g_part + ((size_t)ks * BATCH + gm0) * NOUT;
#pragma unroll
    for (int f = 0; f < 4; f++) {
        int n = wn * 32 + f * 8 + q;
        *(float2*)(pbase + n)            = make_float2(acc[f][0], acc[f][1]);
        *(float2*)(pbase + 8 * NOUT + n) = make_float2(acc[f][2], acc[f][3]);
    }
}

// ---------- Kernel 3: reduce split-K partials + bias ----------
__global__ __launch_bounds__(256) void k_reduce(const float* __restrict__ bias,
                                                float* __restrict__ out) {
    int t = blockIdx.x * 256 + threadIdx.x;     // 0..16383
    float s = bias[t & (NOUT - 1)];
    const float* p = g_part + t;
#pragma unroll 16
    for (int ks = 0; ks < KSPLIT; ks++)
        s += p[(size_t)ks * BATCH * NOUT];
    out[t] = s;
}

extern "C" void kernel_launch(void* const* d_in, const int* in_sizes, int n_in,
                              void* d_out, int out_size) {
    const float* x = (const float*)d_in[0];
    const float* W = (const float*)d_in[1];
    const float* b = (const float*)d_in[2];

    cudaFuncSetAttribute(k_gemm_mma, cudaFuncAttributeMaxDynamicSharedMemorySize,
                         SMEM_ALLOC);

    k_wtransform<<<(NOUT * IN_FEATS / 8) / 256, 256>>>(W);
    k_gemm_mma<<<dim3(KSPLIT, BATCH / 128), 512, SMEM_ALLOC>>>(x);
    k_reduce<<<(BATCH * NOUT) / 256, 256>>>(b, (float*)d_out);
}